// round 5
// baseline (speedup 1.0000x reference)
#include <cuda_runtime.h>
#include <math.h>

#define NN  100000
#define EE  1600000
#define INC 64
#define HIDD 128
#define LN_EPS 1e-5f

// ---------------- scratch (static device globals; no allocation) ----------------
__device__ unsigned g_agg0[NN * INC];    // encoded signed-max accumulator, layer 0
__device__ unsigned g_agg1[NN * HIDD];   // raw-bits max accumulator (values >= 0), layer 1
__device__ float    g_h0  [NN * HIDD];   // layer-0 output (post LN+ReLU)
__device__ int      g_is64;              // 1 if edge_index is int64, 0 if int32

// Monotone float<->uint encode so unsigned max == float max (handles negatives).
__device__ __forceinline__ unsigned enc_f(float f) {
    unsigned u = __float_as_uint(f);
    return (u & 0x80000000u) ? ~u : (u | 0x80000000u);
}
__device__ __forceinline__ float dec_f(unsigned e) {
    return __uint_as_float((e & 0x80000000u) ? (e & 0x7FFFFFFFu) : ~e);
}
// enc_f(-inf) == 0x007FFFFF  -> init value for layer-0 accumulator
#define ENC_NEG_INF 0x007FFFFFu

// ---------------- dtype detection for edge_index ----------------
// If int64 (little-endian) with values < 2^31, every odd int32 word of the src
// row is 0. If int32, odd words are random indices in [0,100000): P(64 zeros)~0.
__global__ void k_detect(const int* __restrict__ eidx) {
    if (threadIdx.x == 0 && blockIdx.x == 0) {
        int all0 = 1;
        #pragma unroll 1
        for (int i = 0; i < 64; i++)
            if (eidx[2 * i + 1] != 0) all0 = 0;
        g_is64 = all0;
    }
}

// ---------------- init accumulators ----------------
__global__ void k_init() {
    long i = (long)blockIdx.x * blockDim.x + threadIdx.x;
    long stride = (long)gridDim.x * blockDim.x;
    for (long t = i; t < (long)NN * INC; t += stride)  g_agg0[t] = ENC_NEG_INF;
    for (long t = i; t < (long)NN * HIDD; t += stride) g_agg1[t] = 0u;
}

// ---------------- layer-0 scatter-max: warp per edge, 64 feats (float2/lane) ----------------
__global__ void __launch_bounds__(256) k_scatter0(const float* __restrict__ x,
                                                  const void* __restrict__ eidx) {
    int warp = (blockIdx.x * blockDim.x + threadIdx.x) >> 5;
    int lane = threadIdx.x & 31;
    if (warp >= EE) return;
    int s, d;
    if (g_is64) {
        const long long* p = (const long long*)eidx;
        s = (int)p[warp]; d = (int)p[EE + warp];
    } else {
        const int* p = (const int*)eidx;
        s = p[warp]; d = p[EE + warp];
    }
    float2 v = ((const float2*)x)[s * 32 + lane];
    unsigned* dp = &g_agg0[d * 64 + lane * 2];
    atomicMax(dp,     enc_f(v.x));
    atomicMax(dp + 1, enc_f(v.y));
}

// ---------------- layer-0 node kernel: linear + bias + LayerNorm + ReLU ----------------
__global__ void __launch_bounds__(128) k_sage0(const float* __restrict__ x,
                                               const float* __restrict__ Wl,
                                               const float* __restrict__ bl,
                                               const float* __restrict__ Wr,
                                               const float* __restrict__ gam,
                                               const float* __restrict__ bet) {
    int node = blockIdx.x;
    int j = threadIdx.x;                  // 0..127 (output feature)
    __shared__ __align__(16) float a[64];
    __shared__ __align__(16) float xr[64];
    __shared__ float rs[4], rq[4];

    if (j < 64) {
        float v = dec_f(g_agg0[node * 64 + j]);
        if (!isfinite(v)) v = 0.f;        // empty neighborhood -> 0 (PyG semantics)
        a[j]  = v;
        xr[j] = x[node * 64 + j];
    }
    __syncthreads();

    const float4* wl4 = (const float4*)(Wl + j * 64);
    const float4* wr4 = (const float4*)(Wr + j * 64);
    const float4* a4  = (const float4*)a;
    const float4* x4  = (const float4*)xr;
    float acc = bl[j];
    #pragma unroll
    for (int k = 0; k < 16; k++) {
        float4 w = wl4[k], v = a4[k];
        acc += w.x * v.x + w.y * v.y + w.z * v.z + w.w * v.w;
    }
    #pragma unroll
    for (int k = 0; k < 16; k++) {
        float4 w = wr4[k], v = x4[k];
        acc += w.x * v.x + w.y * v.y + w.z * v.z + w.w * v.w;
    }

    // block LayerNorm over 128 values
    float s1 = acc, s2 = acc * acc;
    #pragma unroll
    for (int o = 16; o > 0; o >>= 1) {
        s1 += __shfl_xor_sync(0xFFFFFFFFu, s1, o);
        s2 += __shfl_xor_sync(0xFFFFFFFFu, s2, o);
    }
    int w = j >> 5;
    if ((j & 31) == 0) { rs[w] = s1; rq[w] = s2; }
    __syncthreads();
    float sum = rs[0] + rs[1] + rs[2] + rs[3];
    float sq  = rq[0] + rq[1] + rq[2] + rq[3];
    float mu  = sum * (1.f / 128.f);
    float var = sq * (1.f / 128.f) - mu * mu;
    float y = (acc - mu) * rsqrtf(var + LN_EPS) * gam[j] + bet[j];
    g_h0[node * 128 + j] = fmaxf(y, 0.f);
}

// ---------------- layer-1 scatter-max: warp per edge, 128 feats (float4/lane) ----------------
// h0 >= 0, so raw-bits unsigned max == float max, and init 0 == 0.0f handles
// empty neighborhoods for free.
__global__ void __launch_bounds__(256) k_scatter1(const void* __restrict__ eidx) {
    int warp = (blockIdx.x * blockDim.x + threadIdx.x) >> 5;
    int lane = threadIdx.x & 31;
    if (warp >= EE) return;
    int s, d;
    if (g_is64) {
        const long long* p = (const long long*)eidx;
        s = (int)p[warp]; d = (int)p[EE + warp];
    } else {
        const int* p = (const int*)eidx;
        s = p[warp]; d = p[EE + warp];
    }
    float4 v = ((const float4*)g_h0)[s * 32 + lane];
    unsigned* dp = &g_agg1[d * 128 + lane * 4];
    atomicMax(dp,     __float_as_uint(v.x));
    atomicMax(dp + 1, __float_as_uint(v.y));
    atomicMax(dp + 2, __float_as_uint(v.z));
    atomicMax(dp + 3, __float_as_uint(v.w));
}

// ---------------- layer-1 node kernel: linear + LN + ReLU + full MLP head + sigmoid ----------------
__global__ void __launch_bounds__(128) k_sage1(const float* __restrict__ Wl,
                                               const float* __restrict__ bl,
                                               const float* __restrict__ Wr,
                                               const float* __restrict__ gam,
                                               const float* __restrict__ bet,
                                               const float* __restrict__ W1,
                                               const float* __restrict__ b1,
                                               const float* __restrict__ W2,
                                               const float* __restrict__ b2,
                                               float* __restrict__ out) {
    int node = blockIdx.x;
    int j = threadIdx.x;                  // 0..127
    __shared__ __align__(16) float a[128];
    __shared__ __align__(16) float hr[128];
    __shared__ __align__(16) float sOut[128];
    __shared__ float rs[4], rq[4], pr[2];

    a[j]  = __uint_as_float(g_agg1[node * 128 + j]);   // >= 0, empty -> 0
    hr[j] = g_h0[node * 128 + j];
    __syncthreads();

    const float4* wl4 = (const float4*)(Wl + j * 128);
    const float4* wr4 = (const float4*)(Wr + j * 128);
    const float4* a4  = (const float4*)a;
    const float4* h4  = (const float4*)hr;
    float acc = bl[j];
    #pragma unroll
    for (int k = 0; k < 32; k++) {
        float4 w = wl4[k], v = a4[k];
        acc += w.x * v.x + w.y * v.y + w.z * v.z + w.w * v.w;
    }
    #pragma unroll
    for (int k = 0; k < 32; k++) {
        float4 w = wr4[k], v = h4[k];
        acc += w.x * v.x + w.y * v.y + w.z * v.z + w.w * v.w;
    }

    // LayerNorm over 128
    float s1 = acc, s2 = acc * acc;
    #pragma unroll
    for (int o = 16; o > 0; o >>= 1) {
        s1 += __shfl_xor_sync(0xFFFFFFFFu, s1, o);
        s2 += __shfl_xor_sync(0xFFFFFFFFu, s2, o);
    }
    int w = j >> 5;
    if ((j & 31) == 0) { rs[w] = s1; rq[w] = s2; }
    __syncthreads();
    float sum = rs[0] + rs[1] + rs[2] + rs[3];
    float sq  = rq[0] + rq[1] + rq[2] + rq[3];
    float mu  = sum * (1.f / 128.f);
    float var = sq * (1.f / 128.f) - mu * mu;
    float y = (acc - mu) * rsqrtf(var + LN_EPS) * gam[j] + bet[j];
    sOut[j] = fmaxf(y, 0.f);
    __syncthreads();

    // MLP head: hidden(64) = relu(sOut @ W1.T + b1); z = hidden @ W2.T + b2
    float part = 0.f;
    if (j < 64) {
        const float4* w14 = (const float4*)(W1 + j * 128);
        const float4* s4  = (const float4*)sOut;
        float h = b1[j];
        #pragma unroll
        for (int k = 0; k < 32; k++) {
            float4 wv = w14[k], v = s4[k];
            h += wv.x * v.x + wv.y * v.y + wv.z * v.z + wv.w * v.w;
        }
        part = fmaxf(h, 0.f) * W2[j];
    }
    #pragma unroll
    for (int o = 16; o > 0; o >>= 1)
        part += __shfl_xor_sync(0xFFFFFFFFu, part, o);
    if (j == 0)  pr[0] = part;
    if (j == 32) pr[1] = part;
    __syncthreads();
    if (j == 0) {
        float z = pr[0] + pr[1] + b2[0];
        out[node] = 1.f / (1.f + expf(-z));
    }
}

// ---------------- launch ----------------
extern "C" void kernel_launch(void* const* d_in, const int* in_sizes, int n_in,
                              void* d_out, int out_size) {
    const float* x   = (const float*)d_in[0];
    const void*  ei  = d_in[1];
    const float* Wl0 = (const float*)d_in[2];
    const float* bl0 = (const float*)d_in[3];
    const float* Wr0 = (const float*)d_in[4];
    const float* g0  = (const float*)d_in[5];
    const float* be0 = (const float*)d_in[6];
    const float* Wl1 = (const float*)d_in[7];
    const float* bl1 = (const float*)d_in[8];
    const float* Wr1 = (const float*)d_in[9];
    const float* g1  = (const float*)d_in[10];
    const float* be1 = (const float*)d_in[11];
    const float* W1  = (const float*)d_in[12];
    const float* b1  = (const float*)d_in[13];
    const float* W2  = (const float*)d_in[14];
    const float* b2  = (const float*)d_in[15];
    float* out = (float*)d_out;

    k_detect<<<1, 32>>>((const int*)ei);
    k_init<<<2048, 256>>>();
    k_scatter0<<<EE / 8, 256>>>(x, ei);                 // 8 warps/block, warp per edge
    k_sage0<<<NN, 128>>>(x, Wl0, bl0, Wr0, g0, be0);
    k_scatter1<<<EE / 8, 256>>>(ei);
    k_sage1<<<NN, 128>>>(Wl1, bl1, Wr1, g1, be1, W1, b1, W2, b2, out);
}

// round 6
// speedup vs baseline: 2.9850x; 2.9850x over previous
#include <cuda_runtime.h>
#include <math.h>

#define NN   100000
#define EE   1600000
#define INC  64
#define HIDD 128
#define LN_EPS 1e-5f
#define T0   16   // nodes per block, sage0  (100000 = 6250*16)
#define T1   16   // nodes per block, sage1

// ---------------- scratch (static device globals; no allocation) ----------------
__device__ unsigned g_agg0[NN * INC];    // encoded signed-max accumulator, layer 0
__device__ unsigned g_agg1[NN * HIDD];   // raw-bits max accumulator (values >= 0), layer 1
__device__ float    g_h0  [NN * HIDD];   // layer-0 output (post LN+ReLU)
__device__ int      g_is64;              // 1 if edge_index is int64, 0 if int32

// Monotone float<->uint encode so unsigned max == float max (handles negatives).
__device__ __forceinline__ unsigned enc_f(float f) {
    unsigned u = __float_as_uint(f);
    return (u & 0x80000000u) ? ~u : (u | 0x80000000u);
}
__device__ __forceinline__ float dec_f(unsigned e) {
    return __uint_as_float((e & 0x80000000u) ? (e & 0x7FFFFFFFu) : ~e);
}
#define ENC_NEG_INF 0x007FFFFFu   // enc_f(-inf)

// ---------------- dtype detection for edge_index ----------------
__global__ void k_detect(const int* __restrict__ eidx) {
    if (threadIdx.x == 0 && blockIdx.x == 0) {
        int all0 = 1;
        #pragma unroll 1
        for (int i = 0; i < 64; i++)
            if (eidx[2 * i + 1] != 0) all0 = 0;
        g_is64 = all0;
    }
}

// ---------------- init accumulators (vectorized) ----------------
__global__ void k_init() {
    uint4 e4 = make_uint4(ENC_NEG_INF, ENC_NEG_INF, ENC_NEG_INF, ENC_NEG_INF);
    uint4 z4 = make_uint4(0u, 0u, 0u, 0u);
    long i = (long)blockIdx.x * blockDim.x + threadIdx.x;
    long stride = (long)gridDim.x * blockDim.x;
    uint4* p0 = (uint4*)g_agg0;
    uint4* p1 = (uint4*)g_agg1;
    for (long t = i; t < (long)NN * INC / 4; t += stride)  p0[t] = e4;
    for (long t = i; t < (long)NN * HIDD / 4; t += stride) p1[t] = z4;
}

// ---------------- layer-0 scatter-max: warp per edge, float2/lane ----------------
__global__ void __launch_bounds__(256) k_scatter0(const float* __restrict__ x,
                                                  const void* __restrict__ eidx) {
    int warp = (blockIdx.x * blockDim.x + threadIdx.x) >> 5;
    int lane = threadIdx.x & 31;
    if (warp >= EE) return;
    int s, d;
    if (g_is64) {
        const long long* p = (const long long*)eidx;
        s = (int)p[warp]; d = (int)p[EE + warp];
    } else {
        const int* p = (const int*)eidx;
        s = p[warp]; d = p[EE + warp];
    }
    float2 v = ((const float2*)x)[s * 32 + lane];
    unsigned* dp = &g_agg0[d * 64 + lane * 2];
    atomicMax(dp,     enc_f(v.x));
    atomicMax(dp + 1, enc_f(v.y));
}

// ---------------- layer-0 node kernel: register-cached weights, 16-node tile ----------------
__global__ void __launch_bounds__(128) k_sage0(const float* __restrict__ x,
                                               const float* __restrict__ Wl,
                                               const float* __restrict__ bl,
                                               const float* __restrict__ Wr,
                                               const float* __restrict__ gam,
                                               const float* __restrict__ bet) {
    int j = threadIdx.x;                  // output feature 0..127
    int base = blockIdx.x * T0;

    // weight rows in registers (loaded once per block; uncoalesced but amortized x16)
    float wl[64], wr[64];
    {
        const float4* pl = (const float4*)(Wl + j * 64);
        const float4* pr = (const float4*)(Wr + j * 64);
        #pragma unroll
        for (int k = 0; k < 16; k++) {
            float4 a = pl[k]; wl[4*k] = a.x; wl[4*k+1] = a.y; wl[4*k+2] = a.z; wl[4*k+3] = a.w;
            float4 b = pr[k]; wr[4*k] = b.x; wr[4*k+1] = b.y; wr[4*k+2] = b.z; wr[4*k+3] = b.w;
        }
    }
    float gj = gam[j], bj = bet[j], blj = bl[j];

    __shared__ __align__(16) float sa[T0][64];
    __shared__ __align__(16) float sx[T0][64];
    __shared__ float rs[4], rq[4];

    // coalesced staging of tile features
    for (int i = j; i < T0 * 64; i += 128) {
        int n = i >> 6, k = i & 63;
        float v = dec_f(g_agg0[(base + n) * 64 + k]);
        if (!isfinite(v)) v = 0.f;        // empty neighborhood -> 0
        sa[n][k] = v;
        sx[n][k] = x[(base + n) * 64 + k];
    }
    __syncthreads();

    int w = j >> 5;
    for (int n = 0; n < T0; n++) {
        const float4* a4 = (const float4*)sa[n];
        const float4* x4 = (const float4*)sx[n];
        float acc = blj;
        #pragma unroll
        for (int k = 0; k < 16; k++) {
            float4 v = a4[k];             // broadcast LDS (conflict-free)
            acc += wl[4*k] * v.x + wl[4*k+1] * v.y + wl[4*k+2] * v.z + wl[4*k+3] * v.w;
        }
        #pragma unroll
        for (int k = 0; k < 16; k++) {
            float4 v = x4[k];
            acc += wr[4*k] * v.x + wr[4*k+1] * v.y + wr[4*k+2] * v.z + wr[4*k+3] * v.w;
        }
        // LayerNorm over 128
        float s1 = acc, s2 = acc * acc;
        #pragma unroll
        for (int o = 16; o > 0; o >>= 1) {
            s1 += __shfl_xor_sync(0xFFFFFFFFu, s1, o);
            s2 += __shfl_xor_sync(0xFFFFFFFFu, s2, o);
        }
        if ((j & 31) == 0) { rs[w] = s1; rq[w] = s2; }
        __syncthreads();
        float sum = rs[0] + rs[1] + rs[2] + rs[3];
        float sq  = rq[0] + rq[1] + rq[2] + rq[3];
        __syncthreads();                  // protect rs/rq before next node overwrites
        float mu  = sum * (1.f / 128.f);
        float var = sq * (1.f / 128.f) - mu * mu;
        float y = (acc - mu) * rsqrtf(var + LN_EPS) * gj + bj;
        g_h0[(base + n) * 128 + j] = fmaxf(y, 0.f);
    }
}

// ---------------- layer-1 scatter-max: warp per edge, float4/lane ----------------
__global__ void __launch_bounds__(256) k_scatter1(const void* __restrict__ eidx) {
    int warp = (blockIdx.x * blockDim.x + threadIdx.x) >> 5;
    int lane = threadIdx.x & 31;
    if (warp >= EE) return;
    int s, d;
    if (g_is64) {
        const long long* p = (const long long*)eidx;
        s = (int)p[warp]; d = (int)p[EE + warp];
    } else {
        const int* p = (const int*)eidx;
        s = p[warp]; d = p[EE + warp];
    }
    float4 v = ((const float4*)g_h0)[s * 32 + lane];
    unsigned* dp = &g_agg1[d * 128 + lane * 4];
    atomicMax(dp,     __float_as_uint(v.x));
    atomicMax(dp + 1, __float_as_uint(v.y));
    atomicMax(dp + 2, __float_as_uint(v.z));
    atomicMax(dp + 3, __float_as_uint(v.w));
}

// ---------------- layer-1 node kernel: split-row register weights + fused MLP head ----------------
// 256 threads: thread t -> feature j = t&127, half h = t>>7 (owns 64 of the 128-wide row).
// Head: thread t -> out-feat m = t&63, quarter q = t>>6 (owns 32 of W1's 128-wide row).
__global__ void __launch_bounds__(256) k_sage1(const float* __restrict__ Wl,
                                               const float* __restrict__ bl,
                                               const float* __restrict__ Wr,
                                               const float* __restrict__ gam,
                                               const float* __restrict__ bet,
                                               const float* __restrict__ W1,
                                               const float* __restrict__ b1,
                                               const float* __restrict__ W2,
                                               const float* __restrict__ b2,
                                               float* __restrict__ out) {
    int t = threadIdx.x;
    int j = t & 127, h = t >> 7;
    int m = t & 63,  q = t >> 6;
    int base = blockIdx.x * T1;

    float wl[64], wr[64], w1r[32];
    {
        const float4* pl = (const float4*)(Wl + j * 128 + h * 64);
        const float4* pr = (const float4*)(Wr + j * 128 + h * 64);
        #pragma unroll
        for (int k = 0; k < 16; k++) {
            float4 a = pl[k]; wl[4*k] = a.x; wl[4*k+1] = a.y; wl[4*k+2] = a.z; wl[4*k+3] = a.w;
            float4 b = pr[k]; wr[4*k] = b.x; wr[4*k+1] = b.y; wr[4*k+2] = b.z; wr[4*k+3] = b.w;
        }
        const float4* p1 = (const float4*)(W1 + m * 128 + q * 32);
        #pragma unroll
        for (int k = 0; k < 8; k++) {
            float4 a = p1[k]; w1r[4*k] = a.x; w1r[4*k+1] = a.y; w1r[4*k+2] = a.z; w1r[4*k+3] = a.w;
        }
    }
    float gj = gam[j], bj = bet[j], blj = (h == 0) ? bl[j] : 0.f;
    float w2m = W2[m], b1m = b1[m], b2s = b2[0];

    __shared__ __align__(16) float sa[T1][128];
    __shared__ __align__(16) float sh[T1][128];
    __shared__ __align__(16) float part[256];
    __shared__ __align__(16) float sOut[128];
    __shared__ __align__(16) float hpart[256];
    __shared__ float rs[4], rq[4], red[2];

    for (int i = t; i < T1 * 128; i += 256) {
        int n = i >> 7, k = i & 127;
        sa[n][k] = __uint_as_float(g_agg1[(base + n) * 128 + k]);  // >=0, empty->0
        sh[n][k] = g_h0[(base + n) * 128 + k];
    }
    __syncthreads();

    int w = j >> 5;
    for (int n = 0; n < T1; n++) {
        // half-row dot
        const float4* a4 = (const float4*)sa[n] + h * 16;
        const float4* h4 = (const float4*)sh[n] + h * 16;
        float p = blj;
        #pragma unroll
        for (int k = 0; k < 16; k++) {
            float4 v = a4[k];             // broadcast within warp (same h per warp)
            p += wl[4*k] * v.x + wl[4*k+1] * v.y + wl[4*k+2] * v.z + wl[4*k+3] * v.w;
        }
        #pragma unroll
        for (int k = 0; k < 16; k++) {
            float4 v = h4[k];
            p += wr[4*k] * v.x + wr[4*k+1] * v.y + wr[4*k+2] * v.z + wr[4*k+3] * v.w;
        }
        part[t] = p;
        __syncthreads();

        float acc = 0.f;
        if (t < 128) {
            acc = part[j] + part[j + 128];
            float s1 = acc, s2 = acc * acc;
            #pragma unroll
            for (int o = 16; o > 0; o >>= 1) {
                s1 += __shfl_xor_sync(0xFFFFFFFFu, s1, o);
                s2 += __shfl_xor_sync(0xFFFFFFFFu, s2, o);
            }
            if ((j & 31) == 0) { rs[w] = s1; rq[w] = s2; }
        }
        __syncthreads();
        if (t < 128) {
            float sum = rs[0] + rs[1] + rs[2] + rs[3];
            float sq  = rq[0] + rq[1] + rq[2] + rq[3];
            float mu  = sum * (1.f / 128.f);
            float var = sq * (1.f / 128.f) - mu * mu;
            float y = (acc - mu) * rsqrtf(var + LN_EPS) * gj + bj;
            sOut[j] = fmaxf(y, 0.f);
        }
        __syncthreads();

        // MLP head: hidden = relu(sOut @ W1.T + b1); z = hidden @ W2.T + b2
        {
            const float4* s4 = (const float4*)sOut + q * 8;
            float hp = 0.f;
            #pragma unroll
            for (int k = 0; k < 8; k++) {
                float4 v = s4[k];         // broadcast within warp (same q per half-warp? q = t>>6:
                                          // warp 0 has q in {0,1} -> 2-way, still cheap)
                hp += w1r[4*k] * v.x + w1r[4*k+1] * v.y + w1r[4*k+2] * v.z + w1r[4*k+3] * v.w;
            }
            hpart[t] = hp;
            __syncthreads();
            if (t < 64) {
                float hs = hpart[m] + hpart[64 + m] + hpart[128 + m] + hpart[192 + m] + b1m;
                float hv = fmaxf(hs, 0.f) * w2m;
                #pragma unroll
                for (int o = 16; o > 0; o >>= 1)
                    hv += __shfl_xor_sync(0xFFFFFFFFu, hv, o);
                if ((t & 31) == 0) red[t >> 5] = hv;
            }
            __syncthreads();
            if (t == 0) {
                float z = red[0] + red[1] + b2s;
                out[base + n] = 1.f / (1.f + expf(-z));
            }
            __syncthreads();              // protect red/hpart/part/sOut before next node
        }
    }
}

// ---------------- launch ----------------
extern "C" void kernel_launch(void* const* d_in, const int* in_sizes, int n_in,
                              void* d_out, int out_size) {
    const float* x   = (const float*)d_in[0];
    const void*  ei  = d_in[1];
    const float* Wl0 = (const float*)d_in[2];
    const float* bl0 = (const float*)d_in[3];
    const float* Wr0 = (const float*)d_in[4];
    const float* g0  = (const float*)d_in[5];
    const float* be0 = (const float*)d_in[6];
    const float* Wl1 = (const float*)d_in[7];
    const float* bl1 = (const float*)d_in[8];
    const float* Wr1 = (const float*)d_in[9];
    const float* g1  = (const float*)d_in[10];
    const float* be1 = (const float*)d_in[11];
    const float* W1  = (const float*)d_in[12];
    const float* b1  = (const float*)d_in[13];
    const float* W2  = (const float*)d_in[14];
    const float* b2  = (const float*)d_in[15];
    float* out = (float*)d_out;

    k_detect<<<1, 32>>>((const int*)ei);
    k_init<<<2048, 256>>>();
    k_scatter0<<<EE / 8, 256>>>(x, ei);
    k_sage0<<<NN / T0, 128>>>(x, Wl0, bl0, Wr0, g0, be0);
    k_scatter1<<<EE / 8, 256>>>(ei);
    k_sage1<<<NN / T1, 256>>>(Wl1, bl1, Wr1, g1, be1, W1, b1, W2, b2, out);
}

// round 7
// speedup vs baseline: 3.9226x; 1.3141x over previous
#include <cuda_runtime.h>
#include <math.h>

#define NN   100000
#define EE   1600000
#define INC  64
#define HIDD 128
#define LN_EPS 1e-5f
#define T0   16
#define T1   16
#define SB   512                          // scan block width
#define NB0  ((NN + SB - 1) / SB)         // 196 scan blocks

// ---------------- scratch (static device globals; no allocation) ----------------
__device__ int   g_deg[NN];
__device__ int   g_cur[NN];
__device__ int   g_rowTmp[NN];
__device__ int   g_row[NN];
__device__ int   g_bsum[256];
__device__ int   g_boff[256];
__device__ int   g_csr[EE];
__device__ float g_agg0f[NN * INC];
__device__ float g_agg1f[NN * HIDD];
__device__ float g_h0  [NN * HIDD];
__device__ int   g_is64;

// ---------------- dtype detection for edge_index ----------------
__global__ void k_detect(const int* __restrict__ eidx) {
    __shared__ int flag;
    if (threadIdx.x == 0) flag = 1;
    __syncthreads();
    if (threadIdx.x < 64 && eidx[2 * threadIdx.x + 1] != 0) flag = 0;
    __syncthreads();
    if (threadIdx.x == 0) g_is64 = flag;
}

__device__ __forceinline__ void load_edge(const void* eidx, int e, int& s, int& d) {
    if (g_is64) {
        const long long* p = (const long long*)eidx;
        s = (int)p[e]; d = (int)p[EE + e];
    } else {
        const int* p = (const int*)eidx;
        s = p[e]; d = p[EE + e];
    }
}

// ---------------- CSR build ----------------
__global__ void k_zero() {
    int g = blockIdx.x * blockDim.x + threadIdx.x;
    if (g < NN) g_deg[g] = 0;
}

__global__ void __launch_bounds__(256) k_count(const void* __restrict__ eidx) {
    int e = blockIdx.x * 256 + threadIdx.x;
    if (e >= EE) return;
    int d;
    if (g_is64) d = (int)((const long long*)eidx)[EE + e];
    else        d = ((const int*)eidx)[EE + e];
    atomicAdd(&g_deg[d], 1);
}

__global__ void __launch_bounds__(SB) k_scan1() {
    __shared__ int s[SB];
    int tid = threadIdx.x;
    int g = blockIdx.x * SB + tid;
    int v = (g < NN) ? g_deg[g] : 0;
    s[tid] = v;
    __syncthreads();
    for (int off = 1; off < SB; off <<= 1) {
        int t = (tid >= off) ? s[tid - off] : 0;
        __syncthreads();
        s[tid] += t;
        __syncthreads();
    }
    if (g < NN) g_rowTmp[g] = s[tid] - v;       // exclusive within block
    if (tid == SB - 1) g_bsum[blockIdx.x] = s[tid];
}

__global__ void __launch_bounds__(256) k_scan2() {
    __shared__ int s[256];
    int tid = threadIdx.x;
    int v = (tid < NB0) ? g_bsum[tid] : 0;
    s[tid] = v;
    __syncthreads();
    for (int off = 1; off < 256; off <<= 1) {
        int t = (tid >= off) ? s[tid - off] : 0;
        __syncthreads();
        s[tid] += t;
        __syncthreads();
    }
    if (tid < NB0) g_boff[tid] = s[tid] - v;    // exclusive block offsets
}

__global__ void k_scan3() {
    int g = blockIdx.x * blockDim.x + threadIdx.x;
    if (g < NN) {
        int r = g_rowTmp[g] + g_boff[g / SB];
        g_row[g] = r;
        g_cur[g] = r;
    }
}

__global__ void __launch_bounds__(256) k_fill(const void* __restrict__ eidx) {
    int e = blockIdx.x * 256 + threadIdx.x;
    if (e >= EE) return;
    int s, d;
    load_edge(eidx, e, s, d);
    int pos = atomicAdd(&g_cur[d], 1);
    g_csr[pos] = s;
}

// ---------------- gather-max aggregation: warp per node ----------------
__global__ void __launch_bounds__(256) k_agg0(const float* __restrict__ x) {
    int gw = (blockIdx.x * 256 + threadIdx.x) >> 5;
    int lane = threadIdx.x & 31;
    if (gw >= NN) return;
    int row = g_row[gw], deg = g_deg[gw];
    float2 acc = make_float2(-__builtin_huge_valf(), -__builtin_huge_valf());
    for (int b = 0; b < deg; b += 32) {
        int n = min(32, deg - b);
        int myi = (b + lane < deg) ? g_csr[row + b + lane] : 0;
        for (int i = 0; i < n; i++) {
            int s = __shfl_sync(0xFFFFFFFFu, myi, i);
            float2 v = ((const float2*)x)[s * 32 + lane];
            acc.x = fmaxf(acc.x, v.x);
            acc.y = fmaxf(acc.y, v.y);
        }
    }
    if (deg == 0) { acc.x = 0.f; acc.y = 0.f; }   // empty neighborhood -> 0
    ((float2*)g_agg0f)[gw * 32 + lane] = acc;
}

__global__ void __launch_bounds__(256) k_agg1() {
    int gw = (blockIdx.x * 256 + threadIdx.x) >> 5;
    int lane = threadIdx.x & 31;
    if (gw >= NN) return;
    int row = g_row[gw], deg = g_deg[gw];
    // h0 >= 0, so init 0 == max(vals) for nonempty and correct 0 for empty.
    float4 acc = make_float4(0.f, 0.f, 0.f, 0.f);
    for (int b = 0; b < deg; b += 32) {
        int n = min(32, deg - b);
        int myi = (b + lane < deg) ? g_csr[row + b + lane] : 0;
        for (int i = 0; i < n; i++) {
            int s = __shfl_sync(0xFFFFFFFFu, myi, i);
            float4 v = ((const float4*)g_h0)[s * 32 + lane];
            acc.x = fmaxf(acc.x, v.x);
            acc.y = fmaxf(acc.y, v.y);
            acc.z = fmaxf(acc.z, v.z);
            acc.w = fmaxf(acc.w, v.w);
        }
    }
    ((float4*)g_agg1f)[gw * 32 + lane] = acc;
}

// ---------------- layer-0 node kernel: register-cached weights, 16-node tile ----------------
__global__ void __launch_bounds__(128) k_sage0(const float* __restrict__ x,
                                               const float* __restrict__ Wl,
                                               const float* __restrict__ bl,
                                               const float* __restrict__ Wr,
                                               const float* __restrict__ gam,
                                               const float* __restrict__ bet) {
    int j = threadIdx.x;
    int base = blockIdx.x * T0;

    float wl[64], wr[64];
    {
        const float4* pl = (const float4*)(Wl + j * 64);
        const float4* pr = (const float4*)(Wr + j * 64);
        #pragma unroll
        for (int k = 0; k < 16; k++) {
            float4 a = pl[k]; wl[4*k] = a.x; wl[4*k+1] = a.y; wl[4*k+2] = a.z; wl[4*k+3] = a.w;
            float4 b = pr[k]; wr[4*k] = b.x; wr[4*k+1] = b.y; wr[4*k+2] = b.z; wr[4*k+3] = b.w;
        }
    }
    float gj = gam[j], bj = bet[j], blj = bl[j];

    __shared__ __align__(16) float sa[T0][64];
    __shared__ __align__(16) float sx[T0][64];
    __shared__ float rs[4], rq[4];

    for (int i = j; i < T0 * 64; i += 128) {
        int n = i >> 6, k = i & 63;
        sa[n][k] = g_agg0f[(base + n) * 64 + k];
        sx[n][k] = x[(base + n) * 64 + k];
    }
    __syncthreads();

    int w = j >> 5;
    for (int n = 0; n < T0; n++) {
        const float4* a4 = (const float4*)sa[n];
        const float4* x4 = (const float4*)sx[n];
        float acc = blj;
        #pragma unroll
        for (int k = 0; k < 16; k++) {
            float4 v = a4[k];
            acc += wl[4*k] * v.x + wl[4*k+1] * v.y + wl[4*k+2] * v.z + wl[4*k+3] * v.w;
        }
        #pragma unroll
        for (int k = 0; k < 16; k++) {
            float4 v = x4[k];
            acc += wr[4*k] * v.x + wr[4*k+1] * v.y + wr[4*k+2] * v.z + wr[4*k+3] * v.w;
        }
        float s1 = acc, s2 = acc * acc;
        #pragma unroll
        for (int o = 16; o > 0; o >>= 1) {
            s1 += __shfl_xor_sync(0xFFFFFFFFu, s1, o);
            s2 += __shfl_xor_sync(0xFFFFFFFFu, s2, o);
        }
        if ((j & 31) == 0) { rs[w] = s1; rq[w] = s2; }
        __syncthreads();
        float sum = rs[0] + rs[1] + rs[2] + rs[3];
        float sq  = rq[0] + rq[1] + rq[2] + rq[3];
        __syncthreads();
        float mu  = sum * (1.f / 128.f);
        float var = sq * (1.f / 128.f) - mu * mu;
        float y = (acc - mu) * rsqrtf(var + LN_EPS) * gj + bj;
        g_h0[(base + n) * 128 + j] = fmaxf(y, 0.f);
    }
}

// ---------------- layer-1 node kernel: split-row register weights + fused MLP head ----------------
__global__ void __launch_bounds__(256) k_sage1(const float* __restrict__ Wl,
                                               const float* __restrict__ bl,
                                               const float* __restrict__ Wr,
                                               const float* __restrict__ gam,
                                               const float* __restrict__ bet,
                                               const float* __restrict__ W1,
                                               const float* __restrict__ b1,
                                               const float* __restrict__ W2,
                                               const float* __restrict__ b2,
                                               float* __restrict__ out) {
    int t = threadIdx.x;
    int j = t & 127, h = t >> 7;
    int m = t & 63,  q = t >> 6;
    int base = blockIdx.x * T1;

    float wl[64], wr[64], w1r[32];
    {
        const float4* pl = (const float4*)(Wl + j * 128 + h * 64);
        const float4* pr = (const float4*)(Wr + j * 128 + h * 64);
        #pragma unroll
        for (int k = 0; k < 16; k++) {
            float4 a = pl[k]; wl[4*k] = a.x; wl[4*k+1] = a.y; wl[4*k+2] = a.z; wl[4*k+3] = a.w;
            float4 b = pr[k]; wr[4*k] = b.x; wr[4*k+1] = b.y; wr[4*k+2] = b.z; wr[4*k+3] = b.w;
        }
        const float4* p1 = (const float4*)(W1 + m * 128 + q * 32);
        #pragma unroll
        for (int k = 0; k < 8; k++) {
            float4 a = p1[k]; w1r[4*k] = a.x; w1r[4*k+1] = a.y; w1r[4*k+2] = a.z; w1r[4*k+3] = a.w;
        }
    }
    float gj = gam[j], bj = bet[j], blj = (h == 0) ? bl[j] : 0.f;
    float w2m = W2[m], b1m = b1[m], b2s = b2[0];

    __shared__ __align__(16) float sa[T1][128];
    __shared__ __align__(16) float sh[T1][128];
    __shared__ __align__(16) float part[256];
    __shared__ __align__(16) float sOut[128];
    __shared__ __align__(16) float hpart[256];
    __shared__ float rs[4], rq[4], red[2];

    for (int i = t; i < T1 * 128; i += 256) {
        int n = i >> 7, k = i & 127;
        sa[n][k] = g_agg1f[(base + n) * 128 + k];
        sh[n][k] = g_h0[(base + n) * 128 + k];
    }
    __syncthreads();

    int w = j >> 5;
    for (int n = 0; n < T1; n++) {
        const float4* a4 = (const float4*)sa[n] + h * 16;
        const float4* h4 = (const float4*)sh[n] + h * 16;
        float p = blj;
        #pragma unroll
        for (int k = 0; k < 16; k++) {
            float4 v = a4[k];
            p += wl[4*k] * v.x + wl[4*k+1] * v.y + wl[4*k+2] * v.z + wl[4*k+3] * v.w;
        }
        #pragma unroll
        for (int k = 0; k < 16; k++) {
            float4 v = h4[k];
            p += wr[4*k] * v.x + wr[4*k+1] * v.y + wr[4*k+2] * v.z + wr[4*k+3] * v.w;
        }
        part[t] = p;
        __syncthreads();

        float acc = 0.f;
        if (t < 128) {
            acc = part[j] + part[j + 128];
            float s1 = acc, s2 = acc * acc;
            #pragma unroll
            for (int o = 16; o > 0; o >>= 1) {
                s1 += __shfl_xor_sync(0xFFFFFFFFu, s1, o);
                s2 += __shfl_xor_sync(0xFFFFFFFFu, s2, o);
            }
            if ((j & 31) == 0) { rs[w] = s1; rq[w] = s2; }
        }
        __syncthreads();
        if (t < 128) {
            float sum = rs[0] + rs[1] + rs[2] + rs[3];
            float sq  = rq[0] + rq[1] + rq[2] + rq[3];
            float mu  = sum * (1.f / 128.f);
            float var = sq * (1.f / 128.f) - mu * mu;
            float y = (acc - mu) * rsqrtf(var + LN_EPS) * gj + bj;
            sOut[j] = fmaxf(y, 0.f);
        }
        __syncthreads();

        {
            const float4* s4 = (const float4*)sOut + q * 8;
            float hp = 0.f;
            #pragma unroll
            for (int k = 0; k < 8; k++) {
                float4 v = s4[k];
                hp += w1r[4*k] * v.x + w1r[4*k+1] * v.y + w1r[4*k+2] * v.z + w1r[4*k+3] * v.w;
            }
            hpart[t] = hp;
            __syncthreads();
            if (t < 64) {
                float hs = hpart[m] + hpart[64 + m] + hpart[128 + m] + hpart[192 + m] + b1m;
                float hv = fmaxf(hs, 0.f) * w2m;
                #pragma unroll
                for (int o = 16; o > 0; o >>= 1)
                    hv += __shfl_xor_sync(0xFFFFFFFFu, hv, o);
                if ((t & 31) == 0) red[t >> 5] = hv;
            }
            __syncthreads();
            if (t == 0) {
                float z = red[0] + red[1] + b2s;
                out[base + n] = 1.f / (1.f + expf(-z));
            }
            __syncthreads();
        }
    }
}

// ---------------- launch ----------------
extern "C" void kernel_launch(void* const* d_in, const int* in_sizes, int n_in,
                              void* d_out, int out_size) {
    const float* x   = (const float*)d_in[0];
    const void*  ei  = d_in[1];
    const float* Wl0 = (const float*)d_in[2];
    const float* bl0 = (const float*)d_in[3];
    const float* Wr0 = (const float*)d_in[4];
    const float* g0  = (const float*)d_in[5];
    const float* be0 = (const float*)d_in[6];
    const float* Wl1 = (const float*)d_in[7];
    const float* bl1 = (const float*)d_in[8];
    const float* Wr1 = (const float*)d_in[9];
    const float* g1  = (const float*)d_in[10];
    const float* be1 = (const float*)d_in[11];
    const float* W1  = (const float*)d_in[12];
    const float* b1  = (const float*)d_in[13];
    const float* W2  = (const float*)d_in[14];
    const float* b2  = (const float*)d_in[15];
    float* out = (float*)d_out;

    k_detect<<<1, 64>>>((const int*)ei);
    k_zero<<<(NN + 1023) / 1024, 1024>>>();
    k_count<<<(EE + 255) / 256, 256>>>(ei);
    k_scan1<<<NB0, SB>>>();
    k_scan2<<<1, 256>>>();
    k_scan3<<<(NN + 1023) / 1024, 1024>>>();
    k_fill<<<(EE + 255) / 256, 256>>>(ei);
    k_agg0<<<(NN * 32 + 255) / 256, 256>>>(x);
    k_sage0<<<NN / T0, 128>>>(x, Wl0, bl0, Wr0, g0, be0);
    k_agg1<<<(NN * 32 + 255) / 256, 256>>>();
    k_sage1<<<NN / T1, 256>>>(Wl1, bl1, Wr1, g1, be1, W1, b1, W2, b2, out);
}

// round 10
// speedup vs baseline: 4.0474x; 1.0318x over previous
#include <cuda_runtime.h>
#include <math.h>

#define NN   100000
#define EE   1600000
#define INC  64
#define HIDD 128
#define LN_EPS 1e-5f
#define T0   16
#define T1   16
#define SB   512                          // scan block width
#define NB0  ((NN + SB - 1) / SB)         // 196 scan blocks

// ---------------- scratch (static device globals; no allocation) ----------------
__device__ int   g_deg[NN];
__device__ int   g_cur[NN];
__device__ int   g_rowTmp[NN];
__device__ int   g_row[NN];
__device__ int   g_bsum[256];
__device__ int   g_boff[256];
__device__ int   g_csr[EE];
__device__ float g_agg0f[NN * INC];
__device__ float g_agg1f[NN * HIDD];
__device__ float g_h0  [NN * HIDD];
__device__ int   g_is64;

// ---------------- dtype detection for edge_index ----------------
__global__ void k_detect(const int* __restrict__ eidx) {
    __shared__ int flag;
    if (threadIdx.x == 0) flag = 1;
    __syncthreads();
    if (threadIdx.x < 64 && eidx[2 * threadIdx.x + 1] != 0) flag = 0;
    __syncthreads();
    if (threadIdx.x == 0) g_is64 = flag;
}

__device__ __forceinline__ void load_edge(const void* eidx, int e, int& s, int& d) {
    if (g_is64) {
        const long long* p = (const long long*)eidx;
        s = (int)p[e]; d = (int)p[EE + e];
    } else {
        const int* p = (const int*)eidx;
        s = p[e]; d = p[EE + e];
    }
}

// ---------------- CSR build ----------------
__global__ void k_zero() {
    int g = blockIdx.x * blockDim.x + threadIdx.x;
    if (g < NN) g_deg[g] = 0;
}

__global__ void __launch_bounds__(256) k_count(const void* __restrict__ eidx) {
    int e = blockIdx.x * 256 + threadIdx.x;
    if (e >= EE) return;
    int d;
    if (g_is64) d = (int)((const long long*)eidx)[EE + e];
    else        d = ((const int*)eidx)[EE + e];
    atomicAdd(&g_deg[d], 1);
}

__global__ void __launch_bounds__(SB) k_scan1() {
    __shared__ int s[SB];
    int tid = threadIdx.x;
    int g = blockIdx.x * SB + tid;
    int v = (g < NN) ? g_deg[g] : 0;
    s[tid] = v;
    __syncthreads();
    for (int off = 1; off < SB; off <<= 1) {
        int t = (tid >= off) ? s[tid - off] : 0;
        __syncthreads();
        s[tid] += t;
        __syncthreads();
    }
    if (g < NN) g_rowTmp[g] = s[tid] - v;
    if (tid == SB - 1) g_bsum[blockIdx.x] = s[tid];
}

__global__ void __launch_bounds__(256) k_scan2() {
    __shared__ int s[256];
    int tid = threadIdx.x;
    int v = (tid < NB0) ? g_bsum[tid] : 0;
    s[tid] = v;
    __syncthreads();
    for (int off = 1; off < 256; off <<= 1) {
        int t = (tid >= off) ? s[tid - off] : 0;
        __syncthreads();
        s[tid] += t;
        __syncthreads();
    }
    if (tid < NB0) g_boff[tid] = s[tid] - v;
}

__global__ void k_scan3() {
    int g = blockIdx.x * blockDim.x + threadIdx.x;
    if (g < NN) {
        int r = g_rowTmp[g] + g_boff[g / SB];
        g_row[g] = r;
        g_cur[g] = r;
    }
}

__global__ void __launch_bounds__(256) k_fill(const void* __restrict__ eidx) {
    int e = blockIdx.x * 256 + threadIdx.x;
    if (e >= EE) return;
    int s, d;
    load_edge(eidx, e, s, d);
    int pos = atomicAdd(&g_cur[d], 1);
    g_csr[pos] = s;
}

// ---------------- gather-max aggregation: warp per node ----------------
// Indices staged through shared (LDS broadcast) instead of per-iteration SHFL.
__global__ void __launch_bounds__(256) k_agg0(const float* __restrict__ x) {
    __shared__ int sidx[8][32];
    int wloc = threadIdx.x >> 5;
    int gw = (blockIdx.x * 256 + threadIdx.x) >> 5;
    int lane = threadIdx.x & 31;
    if (gw >= NN) return;
    int row = g_row[gw], deg = g_deg[gw];
    float2 acc = make_float2(-__builtin_huge_valf(), -__builtin_huge_valf());
    for (int b = 0; b < deg; b += 32) {
        int n = min(32, deg - b);
        if (b + lane < deg) sidx[wloc][lane] = g_csr[row + b + lane];
        __syncwarp();
        #pragma unroll 4
        for (int i = 0; i < n; i++) {
            int s = sidx[wloc][i];
            float2 v = ((const float2*)x)[s * 32 + lane];
            acc.x = fmaxf(acc.x, v.x);
            acc.y = fmaxf(acc.y, v.y);
        }
        __syncwarp();
    }
    if (deg == 0) { acc.x = 0.f; acc.y = 0.f; }
    ((float2*)g_agg0f)[gw * 32 + lane] = acc;
}

__global__ void __launch_bounds__(256) k_agg1() {
    __shared__ int sidx[8][32];
    int wloc = threadIdx.x >> 5;
    int gw = (blockIdx.x * 256 + threadIdx.x) >> 5;
    int lane = threadIdx.x & 31;
    if (gw >= NN) return;
    int row = g_row[gw], deg = g_deg[gw];
    float4 acc = make_float4(0.f, 0.f, 0.f, 0.f);   // h0 >= 0; empty -> 0
    for (int b = 0; b < deg; b += 32) {
        int n = min(32, deg - b);
        if (b + lane < deg) sidx[wloc][lane] = g_csr[row + b + lane];
        __syncwarp();
        #pragma unroll 4
        for (int i = 0; i < n; i++) {
            int s = sidx[wloc][i];
            float4 v = ((const float4*)g_h0)[s * 32 + lane];
            acc.x = fmaxf(acc.x, v.x);
            acc.y = fmaxf(acc.y, v.y);
            acc.z = fmaxf(acc.z, v.z);
            acc.w = fmaxf(acc.w, v.w);
        }
        __syncwarp();
    }
    ((float4*)g_agg1f)[gw * 32 + lane] = acc;
}

// ---------------- layer-0 node kernel: register weights + 4-way ILP accumulators ----------------
__global__ void __launch_bounds__(128) k_sage0(const float* __restrict__ x,
                                               const float* __restrict__ Wl,
                                               const float* __restrict__ bl,
                                               const float* __restrict__ Wr,
                                               const float* __restrict__ gam,
                                               const float* __restrict__ bet) {
    int j = threadIdx.x;
    int base = blockIdx.x * T0;

    float wl[64], wr[64];
    {
        const float4* pl = (const float4*)(Wl + j * 64);
        const float4* pr = (const float4*)(Wr + j * 64);
        #pragma unroll
        for (int k = 0; k < 16; k++) {
            float4 a = pl[k]; wl[4*k] = a.x; wl[4*k+1] = a.y; wl[4*k+2] = a.z; wl[4*k+3] = a.w;
            float4 b = pr[k]; wr[4*k] = b.x; wr[4*k+1] = b.y; wr[4*k+2] = b.z; wr[4*k+3] = b.w;
        }
    }
    float gj = gam[j], bj = bet[j], blj = bl[j];

    __shared__ __align__(16) float sa[T0][64];
    __shared__ __align__(16) float sx[T0][64];
    __shared__ float rs[4], rq[4];

    for (int i = j; i < T0 * 64; i += 128) {
        int n = i >> 6, k = i & 63;
        sa[n][k] = g_agg0f[(base + n) * 64 + k];
        sx[n][k] = x[(base + n) * 64 + k];
    }
    __syncthreads();

    int w = j >> 5;
    for (int n = 0; n < T0; n++) {
        const float4* a4 = (const float4*)sa[n];
        const float4* x4 = (const float4*)sx[n];
        float c0 = 0.f, c1 = 0.f, c2 = 0.f, c3 = 0.f;   // 4 independent FFMA chains
        #pragma unroll
        for (int k = 0; k < 16; k++) {
            float4 v = a4[k];
            c0 = fmaf(wl[4*k],   v.x, c0);
            c1 = fmaf(wl[4*k+1], v.y, c1);
            c2 = fmaf(wl[4*k+2], v.z, c2);
            c3 = fmaf(wl[4*k+3], v.w, c3);
        }
        #pragma unroll
        for (int k = 0; k < 16; k++) {
            float4 v = x4[k];
            c0 = fmaf(wr[4*k],   v.x, c0);
            c1 = fmaf(wr[4*k+1], v.y, c1);
            c2 = fmaf(wr[4*k+2], v.z, c2);
            c3 = fmaf(wr[4*k+3], v.w, c3);
        }
        float acc = blj + ((c0 + c1) + (c2 + c3));

        float s1 = acc, s2 = acc * acc;
        #pragma unroll
        for (int o = 16; o > 0; o >>= 1) {
            s1 += __shfl_xor_sync(0xFFFFFFFFu, s1, o);
            s2 += __shfl_xor_sync(0xFFFFFFFFu, s2, o);
        }
        if ((j & 31) == 0) { rs[w] = s1; rq[w] = s2; }
        __syncthreads();
        float sum = rs[0] + rs[1] + rs[2] + rs[3];
        float sq  = rq[0] + rq[1] + rq[2] + rq[3];
        __syncthreads();
        float mu  = sum * (1.f / 128.f);
        float var = sq * (1.f / 128.f) - mu * mu;
        float y = (acc - mu) * rsqrtf(var + LN_EPS) * gj + bj;
        g_h0[(base + n) * 128 + j] = fmaxf(y, 0.f);
    }
}

// ---------------- layer-1 node kernel: split-row weights, 4-way ILP, fused head ----------------
__global__ void __launch_bounds__(256) k_sage1(const float* __restrict__ Wl,
                                               const float* __restrict__ bl,
                                               const float* __restrict__ Wr,
                                               const float* __restrict__ gam,
                                               const float* __restrict__ bet,
                                               const float* __restrict__ W1,
                                               const float* __restrict__ b1,
                                               const float* __restrict__ W2,
                                               const float* __restrict__ b2,
                                               float* __restrict__ out) {
    int t = threadIdx.x;
    int j = t & 127, h = t >> 7;
    int m = t & 63,  q = t >> 6;
    int base = blockIdx.x * T1;

    float wl[64], wr[64], w1r[32];
    {
        const float4* pl = (const float4*)(Wl + j * 128 + h * 64);
        const float4* pr = (const float4*)(Wr + j * 128 + h * 64);
        #pragma unroll
        for (int k = 0; k < 16; k++) {
            float4 a = pl[k]; wl[4*k] = a.x; wl[4*k+1] = a.y; wl[4*k+2] = a.z; wl[4*k+3] = a.w;
            float4 b = pr[k]; wr[4*k] = b.x; wr[4*k+1] = b.y; wr[4*k+2] = b.z; wr[4*k+3] = b.w;
        }
        const float4* p1 = (const float4*)(W1 + m * 128 + q * 32);
        #pragma unroll
        for (int k = 0; k < 8; k++) {
            float4 a = p1[k]; w1r[4*k] = a.x; w1r[4*k+1] = a.y; w1r[4*k+2] = a.z; w1r[4*k+3] = a.w;
        }
    }
    float gj = gam[j], bj = bet[j], blj = (h == 0) ? bl[j] : 0.f;
    float w2m = W2[m], b1m = b1[m], b2s = b2[0];

    __shared__ __align__(16) float sa[T1][128];
    __shared__ __align__(16) float sh[T1][128];
    __shared__ __align__(16) float part[256];
    __shared__ __align__(16) float sOut[128];
    __shared__ __align__(16) float hpart[256];
    __shared__ float rs[4], rq[4], red[2];

    for (int i = t; i < T1 * 128; i += 256) {
        int n = i >> 7, k = i & 127;
        sa[n][k] = g_agg1f[(base + n) * 128 + k];
        sh[n][k] = g_h0[(base + n) * 128 + k];
    }
    __syncthreads();

    int w = j >> 5;
    for (int n = 0; n < T1; n++) {
        const float4* a4 = (const float4*)sa[n] + h * 16;
        const float4* h4 = (const float4*)sh[n] + h * 16;
        float c0 = 0.f, c1 = 0.f, c2 = 0.f, c3 = 0.f;
        #pragma unroll
        for (int k = 0; k < 16; k++) {
            float4 v = a4[k];
            c0 = fmaf(wl[4*k],   v.x, c0);
            c1 = fmaf(wl[4*k+1], v.y, c1);
            c2 = fmaf(wl[4*k+2], v.z, c2);
            c3 = fmaf(wl[4*k+3], v.w, c3);
        }
        #pragma unroll
        for (int k = 0; k < 16; k++) {
            float4 v = h4[k];
            c0 = fmaf(wr[4*k],   v.x, c0);
            c1 = fmaf(wr[4*k+1], v.y, c1);
            c2 = fmaf(wr[4*k+2], v.z, c2);
            c3 = fmaf(wr[4*k+3], v.w, c3);
        }
        part[t] = blj + ((c0 + c1) + (c2 + c3));
        __syncthreads();

        float acc = 0.f;
        if (t < 128) {
            acc = part[j] + part[j + 128];
            float s1 = acc, s2 = acc * acc;
            #pragma unroll
            for (int o = 16; o > 0; o >>= 1) {
                s1 += __shfl_xor_sync(0xFFFFFFFFu, s1, o);
                s2 += __shfl_xor_sync(0xFFFFFFFFu, s2, o);
            }
            if ((j & 31) == 0) { rs[w] = s1; rq[w] = s2; }
        }
        __syncthreads();
        if (t < 128) {
            float sum = rs[0] + rs[1] + rs[2] + rs[3];
            float sq  = rq[0] + rq[1] + rq[2] + rq[3];
            float mu  = sum * (1.f / 128.f);
            float var = sq * (1.f / 128.f) - mu * mu;
            float y = (acc - mu) * rsqrtf(var + LN_EPS) * gj + bj;
            sOut[j] = fmaxf(y, 0.f);
        }
        __syncthreads();

        {
            const float4* s4 = (const float4*)sOut + q * 8;
            float d0 = 0.f, d1 = 0.f, d2 = 0.f, d3 = 0.f;
            #pragma unroll
            for (int k = 0; k < 8; k++) {
                float4 v = s4[k];
                d0 = fmaf(w1r[4*k],   v.x, d0);
                d1 = fmaf(w1r[4*k+1], v.y, d1);
                d2 = fmaf(w1r[4*k+2], v.z, d2);
                d3 = fmaf(w1r[4*k+3], v.w, d3);
            }
            hpart[t] = (d0 + d1) + (d2 + d3);
            __syncthreads();
            if (t < 64) {
                float hs = hpart[m] + hpart[64 + m] + hpart[128 + m] + hpart[192 + m] + b1m;
                float hv = fmaxf(hs, 0.f) * w2m;
                #pragma unroll
                for (int o = 16; o > 0; o >>= 1)
                    hv += __shfl_xor_sync(0xFFFFFFFFu, hv, o);
                if ((t & 31) == 0) red[t >> 5] = hv;
            }
            __syncthreads();
            if (t == 0) {
                float z = red[0] + red[1] + b2s;
                out[base + n] = 1.f / (1.f + expf(-z));
            }
            __syncthreads();
        }
    }
}

// ---------------- launch ----------------
extern "C" void kernel_launch(void* const* d_in, const int* in_sizes, int n_in,
                              void* d_out, int out_size) {
    const float* x   = (const float*)d_in[0];
    const void*  ei  = d_in[1];
    const float* Wl0 = (const float*)d_in[2];
    const float* bl0 = (const float*)d_in[3];
    const float* Wr0 = (const float*)d_in[4];
    const float* g0  = (const float*)d_in[5];
    const float* be0 = (const float*)d_in[6];
    const float* Wl1 = (const float*)d_in[7];
    const float* bl1 = (const float*)d_in[8];
    const float* Wr1 = (const float*)d_in[9];
    const float* g1  = (const float*)d_in[10];
    const float* be1 = (const float*)d_in[11];
    const float* W1  = (const float*)d_in[12];
    const float* b1  = (const float*)d_in[13];
    const float* W2  = (const float*)d_in[14];
    const float* b2  = (const float*)d_in[15];
    float* out = (float*)d_out;

    k_detect<<<1, 64>>>((const int*)ei);
    k_zero<<<(NN + 1023) / 1024, 1024>>>();
    k_count<<<(EE + 255) / 256, 256>>>(ei);
    k_scan1<<<NB0, SB>>>();
    k_scan2<<<1, 256>>>();
    k_scan3<<<(NN + 1023) / 1024, 1024>>>();
    k_fill<<<(EE + 255) / 256, 256>>>(ei);
    k_agg0<<<(NN * 32 + 255) / 256, 256>>>(x);
    k_sage0<<<NN / T0, 128>>>(x, Wl0, bl0, Wr0, g0, be0);
    k_agg1<<<(NN * 32 + 255) / 256, 256>>>();
    k_sage1<<<NN / T1, 256>>>(Wl1, bl1, Wr1, g1, be1, W1, b1, W2, b2, out);
}

// round 11
// speedup vs baseline: 5.6660x; 1.3999x over previous
#include <cuda_runtime.h>
#include <math.h>

#define NN   100000
#define EE   1600000
#define INC  64
#define HIDD 128
#define LN_EPS 1e-5f
#define T0   16
#define T1   16
#define SB   512
#define NB0  ((NN + SB - 1) / SB)         // 196 scan blocks

typedef unsigned long long ull;

// ---------------- scratch (static device globals; no allocation) ----------------
__device__ int   g_deg[NN];
__device__ int   g_cur[NN];
__device__ int   g_rowTmp[NN];
__device__ int   g_row[NN];
__device__ int   g_bsum[256];
__device__ int   g_csr[EE];
__device__ float g_agg0f[NN * INC];
__device__ float g_agg1f[NN * HIDD];
__device__ float g_h0  [NN * HIDD];
__device__ int   g_is64;

// ---------------- packed f32x2 helpers ----------------
__device__ __forceinline__ ull pk2(float lo, float hi) {
    ull r; asm("mov.b64 %0,{%1,%2};" : "=l"(r) : "f"(lo), "f"(hi)); return r;
}
__device__ __forceinline__ ull fma2(ull a, ull b, ull c) {
    ull d; asm("fma.rn.f32x2 %0,%1,%2,%3;" : "=l"(d) : "l"(a), "l"(b), "l"(c)); return d;
}
__device__ __forceinline__ float red2(ull v) {
    float lo, hi; asm("mov.b64 {%0,%1},%2;" : "=f"(lo), "=f"(hi) : "l"(v)); return lo + hi;
}

// ---------------- fused detect + degree-zero ----------------
__global__ void k_init2(const int* __restrict__ eidx) {
    int g = blockIdx.x * blockDim.x + threadIdx.x;
    if (g < NN) g_deg[g] = 0;
    if (blockIdx.x == 0) {
        __shared__ int flag;
        if (threadIdx.x == 0) flag = 1;
        __syncthreads();
        if (threadIdx.x < 64 && eidx[2 * threadIdx.x + 1] != 0) flag = 0;
        __syncthreads();
        if (threadIdx.x == 0) g_is64 = flag;
    }
}

__global__ void __launch_bounds__(256) k_count(const void* __restrict__ eidx) {
    int e = blockIdx.x * 256 + threadIdx.x;
    if (e >= EE) return;
    int d;
    if (g_is64) d = (int)((const long long*)eidx)[EE + e];
    else        d = ((const int*)eidx)[EE + e];
    atomicAdd(&g_deg[d], 1);
}

__global__ void __launch_bounds__(SB) k_scan1() {
    __shared__ int s[SB];
    int tid = threadIdx.x;
    int g = blockIdx.x * SB + tid;
    int v = (g < NN) ? g_deg[g] : 0;
    s[tid] = v;
    __syncthreads();
    for (int off = 1; off < SB; off <<= 1) {
        int t = (tid >= off) ? s[tid - off] : 0;
        __syncthreads();
        s[tid] += t;
        __syncthreads();
    }
    if (g < NN) g_rowTmp[g] = s[tid] - v;
    if (tid == SB - 1) g_bsum[blockIdx.x] = s[tid];
}

// fused scan2+scan3: each block recomputes its exclusive block offset (<=196 adds)
__global__ void __launch_bounds__(SB) k_scan23() {
    __shared__ int boff;
    int bi = blockIdx.x;
    if (threadIdx.x < 32) {
        int acc = 0;
        for (int i = threadIdx.x; i < bi; i += 32) acc += g_bsum[i];
        #pragma unroll
        for (int o = 16; o > 0; o >>= 1) acc += __shfl_xor_sync(0xFFFFFFFFu, acc, o);
        if (threadIdx.x == 0) boff = acc;
    }
    __syncthreads();
    int g = bi * SB + threadIdx.x;
    if (g < NN) {
        int r = g_rowTmp[g] + boff;
        g_row[g] = r;
        g_cur[g] = r;
    }
}

__global__ void __launch_bounds__(256) k_fill(const void* __restrict__ eidx) {
    int e = blockIdx.x * 256 + threadIdx.x;
    if (e >= EE) return;
    int s, d;
    if (g_is64) {
        const long long* p = (const long long*)eidx;
        s = (int)p[e]; d = (int)p[EE + e];
    } else {
        const int* p = (const int*)eidx;
        s = p[e]; d = p[EE + e];
    }
    int pos = atomicAdd(&g_cur[d], 1);
    g_csr[pos] = s;
}

// ---------------- gather-max aggregation: warp per node ----------------
__global__ void __launch_bounds__(256) k_agg0(const float* __restrict__ x) {
    __shared__ int sidx[8][32];
    int wloc = threadIdx.x >> 5;
    int gw = (blockIdx.x * 256 + threadIdx.x) >> 5;
    int lane = threadIdx.x & 31;
    if (gw >= NN) return;
    int row = g_row[gw], deg = g_deg[gw];
    float2 acc = make_float2(-__builtin_huge_valf(), -__builtin_huge_valf());
    for (int b = 0; b < deg; b += 32) {
        int n = min(32, deg - b);
        if (b + lane < deg) sidx[wloc][lane] = g_csr[row + b + lane];
        __syncwarp();
        #pragma unroll 8
        for (int i = 0; i < n; i++) {
            int s = sidx[wloc][i];
            float2 v = ((const float2*)x)[s * 32 + lane];
            acc.x = fmaxf(acc.x, v.x);
            acc.y = fmaxf(acc.y, v.y);
        }
        __syncwarp();
    }
    if (deg == 0) { acc.x = 0.f; acc.y = 0.f; }
    ((float2*)g_agg0f)[gw * 32 + lane] = acc;
}

__global__ void __launch_bounds__(256) k_agg1() {
    __shared__ int sidx[8][32];
    int wloc = threadIdx.x >> 5;
    int gw = (blockIdx.x * 256 + threadIdx.x) >> 5;
    int lane = threadIdx.x & 31;
    if (gw >= NN) return;
    int row = g_row[gw], deg = g_deg[gw];
    float4 acc = make_float4(0.f, 0.f, 0.f, 0.f);   // h0 >= 0; empty -> 0
    for (int b = 0; b < deg; b += 32) {
        int n = min(32, deg - b);
        if (b + lane < deg) sidx[wloc][lane] = g_csr[row + b + lane];
        __syncwarp();
        #pragma unroll 8
        for (int i = 0; i < n; i++) {
            int s = sidx[wloc][i];
            float4 v = ((const float4*)g_h0)[s * 32 + lane];
            acc.x = fmaxf(acc.x, v.x);
            acc.y = fmaxf(acc.y, v.y);
            acc.z = fmaxf(acc.z, v.z);
            acc.w = fmaxf(acc.w, v.w);
        }
        __syncwarp();
    }
    ((float4*)g_agg1f)[gw * 32 + lane] = acc;
}

// ---------------- layer-0: phase-amortized, packed-f32x2 ----------------
// 128 threads. Phase A: thread j = full-row dot for all T0 nodes -> part.
// Phase B: warp w handles nodes 4w..4w+3; lane covers 4 features; warp-local LN.
__global__ void __launch_bounds__(128) k_sage0(const float* __restrict__ x,
                                               const float* __restrict__ Wl,
                                               const float* __restrict__ bl,
                                               const float* __restrict__ Wr,
                                               const float* __restrict__ gam,
                                               const float* __restrict__ bet) {
    int j = threadIdx.x;
    int lane = j & 31, w = j >> 5;
    int base = blockIdx.x * T0;

    ull wl2[32], wr2[32];
    {
        const float4* pl = (const float4*)(Wl + j * 64);
        const float4* pr = (const float4*)(Wr + j * 64);
        #pragma unroll
        for (int k = 0; k < 16; k++) {
            float4 a = pl[k]; wl2[2*k] = pk2(a.x, a.y); wl2[2*k+1] = pk2(a.z, a.w);
            float4 b = pr[k]; wr2[2*k] = pk2(b.x, b.y); wr2[2*k+1] = pk2(b.z, b.w);
        }
    }
    float blj = bl[j];
    float gv[4], bv[4];
    #pragma unroll
    for (int i = 0; i < 4; i++) { gv[i] = gam[lane + 32*i]; bv[i] = bet[lane + 32*i]; }

    __shared__ __align__(16) float sa[T0][64];
    __shared__ __align__(16) float sx[T0][64];
    __shared__ __align__(16) float part[T0][128];

    for (int i = j; i < T0 * 64; i += 128) {
        int n = i >> 6, k = i & 63;
        sa[n][k] = g_agg0f[(base + n) * 64 + k];
        sx[n][k] = x[(base + n) * 64 + k];
    }
    __syncthreads();

    // Phase A
    for (int n = 0; n < T0; n++) {
        const ulonglong2* a2 = (const ulonglong2*)sa[n];
        const ulonglong2* x2 = (const ulonglong2*)sx[n];
        ull c0 = 0, c1 = 0, c2 = 0, c3 = 0;       // packed zero == (0.f,0.f)
        #pragma unroll
        for (int k = 0; k < 16; k++) {
            ulonglong2 pa = a2[k];
            ulonglong2 px = x2[k];
            c0 = fma2(wl2[2*k],   pa.x, c0);
            c1 = fma2(wl2[2*k+1], pa.y, c1);
            c2 = fma2(wr2[2*k],   px.x, c2);
            c3 = fma2(wr2[2*k+1], px.y, c3);
        }
        part[n][j] = blj + ((red2(c0) + red2(c1)) + (red2(c2) + red2(c3)));
    }
    __syncthreads();

    // Phase B: warp w -> nodes 4w..4w+3
    #pragma unroll
    for (int i = 0; i < 4; i++) {
        int n = w * 4 + i;
        float v0 = part[n][lane], v1 = part[n][lane + 32],
              v2 = part[n][lane + 64], v3 = part[n][lane + 96];
        float s1 = (v0 + v1) + (v2 + v3);
        float s2 = (v0*v0 + v1*v1) + (v2*v2 + v3*v3);
        #pragma unroll
        for (int o = 16; o > 0; o >>= 1) {
            s1 += __shfl_xor_sync(0xFFFFFFFFu, s1, o);
            s2 += __shfl_xor_sync(0xFFFFFFFFu, s2, o);
        }
        float mu = s1 * (1.f / 128.f);
        float var = s2 * (1.f / 128.f) - mu * mu;
        float rstd = rsqrtf(var + LN_EPS);
        float* dst = g_h0 + (base + n) * 128 + lane;
        dst[0]  = fmaxf((v0 - mu) * rstd * gv[0] + bv[0], 0.f);
        dst[32] = fmaxf((v1 - mu) * rstd * gv[1] + bv[1], 0.f);
        dst[64] = fmaxf((v2 - mu) * rstd * gv[2] + bv[2], 0.f);
        dst[96] = fmaxf((v3 - mu) * rstd * gv[3] + bv[3], 0.f);
    }
}

// ---------------- layer-1: phase-amortized, packed-f32x2, fused MLP head ----------------
// 256 threads. A: thread t (j=t&127,h=t>>7) half-row dots -> part[n][t].
// B: warp w -> nodes 2w,2w+1: combine halves + LN + ReLU -> sOut.
// C1: thread t (m=t&63,q=t>>6) partial head dot -> part[n][t] (reuse).
// C2: warp w -> nodes 2w,2w+1: combine, relu*W2, reduce, sigmoid -> out.
__global__ void __launch_bounds__(256) k_sage1(const float* __restrict__ Wl,
                                               const float* __restrict__ bl,
                                               const float* __restrict__ Wr,
                                               const float* __restrict__ gam,
                                               const float* __restrict__ bet,
                                               const float* __restrict__ W1,
                                               const float* __restrict__ b1,
                                               const float* __restrict__ W2,
                                               const float* __restrict__ b2,
                                               float* __restrict__ out) {
    int t = threadIdx.x;
    int j = t & 127, h = t >> 7;
    int m = t & 63,  q = t >> 6;
    int lane = t & 31, w = t >> 5;
    int base = blockIdx.x * T1;

    ull wl2[32], wr2[32], w1p[16];
    {
        const float4* pl = (const float4*)(Wl + j * 128 + h * 64);
        const float4* pr = (const float4*)(Wr + j * 128 + h * 64);
        #pragma unroll
        for (int k = 0; k < 16; k++) {
            float4 a = pl[k]; wl2[2*k] = pk2(a.x, a.y); wl2[2*k+1] = pk2(a.z, a.w);
            float4 b = pr[k]; wr2[2*k] = pk2(b.x, b.y); wr2[2*k+1] = pk2(b.z, b.w);
        }
        const float4* p1 = (const float4*)(W1 + m * 128 + q * 32);
        #pragma unroll
        for (int k = 0; k < 8; k++) {
            float4 a = p1[k]; w1p[2*k] = pk2(a.x, a.y); w1p[2*k+1] = pk2(a.z, a.w);
        }
    }
    float blj = (h == 0) ? bl[j] : 0.f;
    float gv[4], bv[4];
    #pragma unroll
    for (int i = 0; i < 4; i++) { gv[i] = gam[lane + 32*i]; bv[i] = bet[lane + 32*i]; }
    float b1v0 = b1[lane], b1v1 = b1[lane + 32];
    float w2v0 = W2[lane], w2v1 = W2[lane + 32];
    float b2s = b2[0];

    __shared__ __align__(16) float sa[T1][128];
    __shared__ __align__(16) float sh[T1][128];
    __shared__ __align__(16) float part[T1][256];
    __shared__ __align__(16) float sOut[T1][128];

    for (int i = t; i < T1 * 128; i += 256) {
        int n = i >> 7, k = i & 127;
        sa[n][k] = g_agg1f[(base + n) * 128 + k];
        sh[n][k] = g_h0[(base + n) * 128 + k];
    }
    __syncthreads();

    // Phase A: half-row dots for all nodes
    for (int n = 0; n < T1; n++) {
        const ulonglong2* a2 = (const ulonglong2*)(sa[n] + h * 64);
        const ulonglong2* h4 = (const ulonglong2*)(sh[n] + h * 64);
        ull c0 = 0, c1 = 0, c2 = 0, c3 = 0;
        #pragma unroll
        for (int k = 0; k < 16; k++) {
            ulonglong2 pa = a2[k];
            ulonglong2 ph = h4[k];
            c0 = fma2(wl2[2*k],   pa.x, c0);
            c1 = fma2(wl2[2*k+1], pa.y, c1);
            c2 = fma2(wr2[2*k],   ph.x, c2);
            c3 = fma2(wr2[2*k+1], ph.y, c3);
        }
        part[n][t] = blj + ((red2(c0) + red2(c1)) + (red2(c2) + red2(c3)));
    }
    __syncthreads();

    // Phase B: warp w -> nodes 2w, 2w+1
    #pragma unroll
    for (int i = 0; i < 2; i++) {
        int n = w * 2 + i;
        float v0 = part[n][lane]      + part[n][lane + 128];
        float v1 = part[n][lane + 32] + part[n][lane + 160];
        float v2 = part[n][lane + 64] + part[n][lane + 192];
        float v3 = part[n][lane + 96] + part[n][lane + 224];
        float s1 = (v0 + v1) + (v2 + v3);
        float s2 = (v0*v0 + v1*v1) + (v2*v2 + v3*v3);
        #pragma unroll
        for (int o = 16; o > 0; o >>= 1) {
            s1 += __shfl_xor_sync(0xFFFFFFFFu, s1, o);
            s2 += __shfl_xor_sync(0xFFFFFFFFu, s2, o);
        }
        float mu = s1 * (1.f / 128.f);
        float var = s2 * (1.f / 128.f) - mu * mu;
        float rstd = rsqrtf(var + LN_EPS);
        sOut[n][lane]      = fmaxf((v0 - mu) * rstd * gv[0] + bv[0], 0.f);
        sOut[n][lane + 32] = fmaxf((v1 - mu) * rstd * gv[1] + bv[1], 0.f);
        sOut[n][lane + 64] = fmaxf((v2 - mu) * rstd * gv[2] + bv[2], 0.f);
        sOut[n][lane + 96] = fmaxf((v3 - mu) * rstd * gv[3] + bv[3], 0.f);
    }
    __syncthreads();

    // Phase C1: head partial dots (reuse part as hpart; part[n][t] == hpart[n][q*64+m])
    for (int n = 0; n < T1; n++) {
        const ulonglong2* s2p = (const ulonglong2*)(sOut[n] + q * 32);
        ull c0 = 0, c1 = 0;
        #pragma unroll
        for (int k = 0; k < 8; k++) {
            ulonglong2 pv = s2p[k];
            c0 = fma2(w1p[2*k],   pv.x, c0);
            c1 = fma2(w1p[2*k+1], pv.y, c1);
        }
        part[n][t] = red2(c0) + red2(c1);
    }
    __syncthreads();

    // Phase C2: warp w -> nodes 2w, 2w+1
    #pragma unroll
    for (int i = 0; i < 2; i++) {
        int n = w * 2 + i;
        float h0 = part[n][lane]      + part[n][64 + lane]
                 + part[n][128 + lane] + part[n][192 + lane] + b1v0;
        float h1 = part[n][32 + lane] + part[n][96 + lane]
                 + part[n][160 + lane] + part[n][224 + lane] + b1v1;
        float z = fmaxf(h0, 0.f) * w2v0 + fmaxf(h1, 0.f) * w2v1;
        #pragma unroll
        for (int o = 16; o > 0; o >>= 1)
            z += __shfl_xor_sync(0xFFFFFFFFu, z, o);
        if (lane == 0)
            out[base + n] = 1.f / (1.f + expf(-(z + b2s)));
    }
}

// ---------------- launch ----------------
extern "C" void kernel_launch(void* const* d_in, const int* in_sizes, int n_in,
                              void* d_out, int out_size) {
    const float* x   = (const float*)d_in[0];
    const void*  ei  = d_in[1];
    const float* Wl0 = (const float*)d_in[2];
    const float* bl0 = (const float*)d_in[3];
    const float* Wr0 = (const float*)d_in[4];
    const float* g0  = (const float*)d_in[5];
    const float* be0 = (const float*)d_in[6];
    const float* Wl1 = (const float*)d_in[7];
    const float* bl1 = (const float*)d_in[8];
    const float* Wr1 = (const float*)d_in[9];
    const float* g1  = (const float*)d_in[10];
    const float* be1 = (const float*)d_in[11];
    const float* W1  = (const float*)d_in[12];
    const float* b1  = (const float*)d_in[13];
    const float* W2  = (const float*)d_in[14];
    const float* b2  = (const float*)d_in[15];
    float* out = (float*)d_out;

    k_init2<<<(NN + 1023) / 1024, 1024>>>((const int*)ei);   // 1
    k_count<<<(EE + 255) / 256, 256>>>(ei);                  // 2
    k_scan1<<<NB0, SB>>>();                                  // 3
    k_scan23<<<NB0, SB>>>();                                 // 4
    k_fill<<<(EE + 255) / 256, 256>>>(ei);                   // 5
    k_agg0<<<(NN * 32 + 255) / 256, 256>>>(x);               // 6  <- ncu -s 5 -c 1 lands here
    k_sage0<<<NN / T0, 128>>>(x, Wl0, bl0, Wr0, g0, be0);    // 7
    k_agg1<<<(NN * 32 + 255) / 256, 256>>>();                // 8
    k_sage1<<<NN / T1, 256>>>(Wl1, bl1, Wr1, g1, be1, W1, b1, W2, b2, out);  // 9
}

// round 13
// speedup vs baseline: 6.2214x; 1.0980x over previous
#include <cuda_runtime.h>
#include <math.h>

#define NN   100000
#define EE   1600000
#define INC  64
#define HIDD 128
#define LN_EPS 1e-5f
#define T0   16
#define T1   16
#define SB   512
#define NB0  ((NN + SB - 1) / SB)         // 196 scan blocks

typedef unsigned long long ull;

// ---------------- scratch (static device globals; no allocation) ----------------
__device__ int   g_deg[NN];
__device__ int   g_cur[NN];
__device__ int   g_rowTmp[NN];
__device__ int   g_row[NN];
__device__ int   g_bsum[256];
__device__ int   g_csr[EE];
__device__ float g_agg0f[NN * INC];
__device__ float g_agg1f[NN * HIDD];
__device__ float g_h0  [NN * HIDD];
__device__ int   g_is64;

// ---------------- packed f32x2 helpers ----------------
__device__ __forceinline__ ull pk2(float lo, float hi) {
    ull r; asm("mov.b64 %0,{%1,%2};" : "=l"(r) : "f"(lo), "f"(hi)); return r;
}
__device__ __forceinline__ ull fma2(ull a, ull b, ull c) {
    ull d; asm("fma.rn.f32x2 %0,%1,%2,%3;" : "=l"(d) : "l"(a), "l"(b), "l"(c)); return d;
}
__device__ __forceinline__ float red2(ull v) {
    float lo, hi; asm("mov.b64 {%0,%1},%2;" : "=f"(lo), "=f"(hi) : "l"(v)); return lo + hi;
}

// ---------------- fused detect + degree-zero ----------------
__global__ void k_init2(const int* __restrict__ eidx) {
    int g = blockIdx.x * blockDim.x + threadIdx.x;
    if (g < NN) g_deg[g] = 0;
    if (blockIdx.x == 0) {
        __shared__ int flag;
        if (threadIdx.x == 0) flag = 1;
        __syncthreads();
        if (threadIdx.x < 64 && eidx[2 * threadIdx.x + 1] != 0) flag = 0;
        __syncthreads();
        if (threadIdx.x == 0) g_is64 = flag;
    }
}

__global__ void __launch_bounds__(256) k_count(const void* __restrict__ eidx) {
    int e = blockIdx.x * 256 + threadIdx.x;
    if (e >= EE) return;
    int d;
    if (g_is64) d = (int)((const long long*)eidx)[EE + e];
    else        d = ((const int*)eidx)[EE + e];
    atomicAdd(&g_deg[d], 1);
}

__global__ void __launch_bounds__(SB) k_scan1() {
    __shared__ int s[SB];
    int tid = threadIdx.x;
    int g = blockIdx.x * SB + tid;
    int v = (g < NN) ? g_deg[g] : 0;
    s[tid] = v;
    __syncthreads();
    for (int off = 1; off < SB; off <<= 1) {
        int t = (tid >= off) ? s[tid - off] : 0;
        __syncthreads();
        s[tid] += t;
        __syncthreads();
    }
    if (g < NN) g_rowTmp[g] = s[tid] - v;
    if (tid == SB - 1) g_bsum[blockIdx.x] = s[tid];
}

__global__ void __launch_bounds__(SB) k_scan23() {
    __shared__ int boff;
    int bi = blockIdx.x;
    if (threadIdx.x < 32) {
        int acc = 0;
        for (int i = threadIdx.x; i < bi; i += 32) acc += g_bsum[i];
        #pragma unroll
        for (int o = 16; o > 0; o >>= 1) acc += __shfl_xor_sync(0xFFFFFFFFu, acc, o);
        if (threadIdx.x == 0) boff = acc;
    }
    __syncthreads();
    int g = bi * SB + threadIdx.x;
    if (g < NN) {
        int r = g_rowTmp[g] + boff;
        g_row[g] = r;
        g_cur[g] = r;
    }
}

__global__ void __launch_bounds__(256) k_fill(const void* __restrict__ eidx) {
    int e = blockIdx.x * 256 + threadIdx.x;
    if (e >= EE) return;
    int s, d;
    if (g_is64) {
        const long long* p = (const long long*)eidx;
        s = (int)p[e]; d = (int)p[EE + e];
    } else {
        const int* p = (const int*)eidx;
        s = p[e]; d = p[EE + e];
    }
    int pos = atomicAdd(&g_cur[d], 1);
    g_csr[pos] = s;
}

// ---------------- gather-max aggregation: warp per node ----------------
__global__ void __launch_bounds__(256) k_agg0(const float* __restrict__ x) {
    __shared__ int sidx[8][32];
    int wloc = threadIdx.x >> 5;
    int gw = (blockIdx.x * 256 + threadIdx.x) >> 5;
    int lane = threadIdx.x & 31;
    if (gw >= NN) return;
    int row = g_row[gw], deg = g_deg[gw];
    float2 acc = make_float2(-__builtin_huge_valf(), -__builtin_huge_valf());
    for (int b = 0; b < deg; b += 32) {
        int n = min(32, deg - b);
        if (b + lane < deg) sidx[wloc][lane] = g_csr[row + b + lane];
        __syncwarp();
        #pragma unroll 8
        for (int i = 0; i < n; i++) {
            int s = sidx[wloc][i];
            float2 v = ((const float2*)x)[s * 32 + lane];
            acc.x = fmaxf(acc.x, v.x);
            acc.y = fmaxf(acc.y, v.y);
        }
        __syncwarp();
    }
    if (deg == 0) { acc.x = 0.f; acc.y = 0.f; }
    ((float2*)g_agg0f)[gw * 32 + lane] = acc;
}

__global__ void __launch_bounds__(256) k_agg1() {
    __shared__ int sidx[8][32];
    int wloc = threadIdx.x >> 5;
    int gw = (blockIdx.x * 256 + threadIdx.x) >> 5;
    int lane = threadIdx.x & 31;
    if (gw >= NN) return;
    int row = g_row[gw], deg = g_deg[gw];
    float4 acc = make_float4(0.f, 0.f, 0.f, 0.f);   // h0 >= 0; empty -> 0
    for (int b = 0; b < deg; b += 32) {
        int n = min(32, deg - b);
        if (b + lane < deg) sidx[wloc][lane] = g_csr[row + b + lane];
        __syncwarp();
        #pragma unroll 8
        for (int i = 0; i < n; i++) {
            int s = sidx[wloc][i];
            float4 v = ((const float4*)g_h0)[s * 32 + lane];
            acc.x = fmaxf(acc.x, v.x);
            acc.y = fmaxf(acc.y, v.y);
            acc.z = fmaxf(acc.z, v.z);
            acc.w = fmaxf(acc.w, v.w);
        }
        __syncwarp();
    }
    ((float4*)g_agg1f)[gw * 32 + lane] = acc;
}

// ---------------- layer-0: 256 threads, half-rows (no spills) ----------------
// Phase A: thread t (j=t&127, h=t>>7) dots half-row (32 floats) -> part[n][t].
// Phase B: warp w -> nodes 2w,2w+1: combine halves + LN + ReLU -> g_h0.
__global__ void __launch_bounds__(256) k_sage0(const float* __restrict__ x,
                                               const float* __restrict__ Wl,
                                               const float* __restrict__ bl,
                                               const float* __restrict__ Wr,
                                               const float* __restrict__ gam,
                                               const float* __restrict__ bet) {
    int t = threadIdx.x;
    int j = t & 127, h = t >> 7;
    int lane = t & 31, w = t >> 5;
    int base = blockIdx.x * T0;

    ull wl2[16], wr2[16];                 // 32 floats each = 64 regs total
    {
        const float4* pl = (const float4*)(Wl + j * 64 + h * 32);
        const float4* pr = (const float4*)(Wr + j * 64 + h * 32);
        #pragma unroll
        for (int k = 0; k < 8; k++) {
            float4 a = pl[k]; wl2[2*k] = pk2(a.x, a.y); wl2[2*k+1] = pk2(a.z, a.w);
            float4 b = pr[k]; wr2[2*k] = pk2(b.x, b.y); wr2[2*k+1] = pk2(b.z, b.w);
        }
    }
    float blj = (h == 0) ? bl[j] : 0.f;
    float gv[4], bv[4];
    #pragma unroll
    for (int i = 0; i < 4; i++) { gv[i] = gam[lane + 32*i]; bv[i] = bet[lane + 32*i]; }

    __shared__ __align__(16) float sa[T0][64];
    __shared__ __align__(16) float sx[T0][64];
    __shared__ __align__(16) float part[T0][256];

    for (int i = t; i < T0 * 64; i += 256) {
        int n = i >> 6, k = i & 63;
        sa[n][k] = g_agg0f[(base + n) * 64 + k];
        sx[n][k] = x[(base + n) * 64 + k];
    }
    __syncthreads();

    // Phase A
    for (int n = 0; n < T0; n++) {
        const ulonglong2* a2 = (const ulonglong2*)(sa[n] + h * 32);
        const ulonglong2* x2 = (const ulonglong2*)(sx[n] + h * 32);
        ull c0 = 0, c1 = 0, c2 = 0, c3 = 0;
        #pragma unroll
        for (int k = 0; k < 8; k++) {
            ulonglong2 pa = a2[k];
            ulonglong2 px = x2[k];
            c0 = fma2(wl2[2*k],   pa.x, c0);
            c1 = fma2(wl2[2*k+1], pa.y, c1);
            c2 = fma2(wr2[2*k],   px.x, c2);
            c3 = fma2(wr2[2*k+1], px.y, c3);
        }
        part[n][t] = blj + ((red2(c0) + red2(c1)) + (red2(c2) + red2(c3)));
    }
    __syncthreads();

    // Phase B: warp w -> nodes 2w, 2w+1
    #pragma unroll
    for (int i = 0; i < 2; i++) {
        int n = w * 2 + i;
        float v0 = part[n][lane]      + part[n][lane + 128];
        float v1 = part[n][lane + 32] + part[n][lane + 160];
        float v2 = part[n][lane + 64] + part[n][lane + 192];
        float v3 = part[n][lane + 96] + part[n][lane + 224];
        float s1 = (v0 + v1) + (v2 + v3);
        float s2 = (v0*v0 + v1*v1) + (v2*v2 + v3*v3);
        #pragma unroll
        for (int o = 16; o > 0; o >>= 1) {
            s1 += __shfl_xor_sync(0xFFFFFFFFu, s1, o);
            s2 += __shfl_xor_sync(0xFFFFFFFFu, s2, o);
        }
        float mu = s1 * (1.f / 128.f);
        float var = s2 * (1.f / 128.f) - mu * mu;
        float rstd = rsqrtf(var + LN_EPS);
        float* dst = g_h0 + (base + n) * 128 + lane;
        dst[0]  = fmaxf((v0 - mu) * rstd * gv[0] + bv[0], 0.f);
        dst[32] = fmaxf((v1 - mu) * rstd * gv[1] + bv[1], 0.f);
        dst[64] = fmaxf((v2 - mu) * rstd * gv[2] + bv[2], 0.f);
        dst[96] = fmaxf((v3 - mu) * rstd * gv[3] + bv[3], 0.f);
    }
}

// ---------------- layer-1: 512 threads, quarter-rows (no spills), fused head ----------------
// A: thread t (j=t&127, hq=t>>7 in 0..3) dots quarter-row (32 floats) -> part[n][t].
// B: warp w -> node w: combine 4 quarters + LN + ReLU -> sOut[n].
// C1: thread t (m=t&63, q=t>>6 in 0..7) 16-float head segment -> part[n][t].
// C2: warp w -> node w: combine 8 segments, relu*W2, reduce, sigmoid.
__global__ void __launch_bounds__(512) k_sage1(const float* __restrict__ Wl,
                                               const float* __restrict__ bl,
                                               const float* __restrict__ Wr,
                                               const float* __restrict__ gam,
                                               const float* __restrict__ bet,
                                               const float* __restrict__ W1,
                                               const float* __restrict__ b1,
                                               const float* __restrict__ W2,
                                               const float* __restrict__ b2,
                                               float* __restrict__ out) {
    int t = threadIdx.x;
    int j = t & 127, hq = t >> 7;         // quarter index 0..3
    int m = t & 63,  q = t >> 6;          // head segment 0..7
    int lane = t & 31, w = t >> 5;        // 16 warps
    int base = blockIdx.x * T1;

    ull wl2[16], wr2[16], w1p[8];         // 64 + 16 regs of weights
    {
        const float4* pl = (const float4*)(Wl + j * 128 + hq * 32);
        const float4* pr = (const float4*)(Wr + j * 128 + hq * 32);
        #pragma unroll
        for (int k = 0; k < 8; k++) {
            float4 a = pl[k]; wl2[2*k] = pk2(a.x, a.y); wl2[2*k+1] = pk2(a.z, a.w);
            float4 b = pr[k]; wr2[2*k] = pk2(b.x, b.y); wr2[2*k+1] = pk2(b.z, b.w);
        }
        const float4* p1 = (const float4*)(W1 + m * 128 + q * 16);
        #pragma unroll
        for (int k = 0; k < 4; k++) {
            float4 a = p1[k]; w1p[2*k] = pk2(a.x, a.y); w1p[2*k+1] = pk2(a.z, a.w);
        }
    }
    float blj = (hq == 0) ? bl[j] : 0.f;
    float gv[4], bv[4];
    #pragma unroll
    for (int i = 0; i < 4; i++) { gv[i] = gam[lane + 32*i]; bv[i] = bet[lane + 32*i]; }
    float b1v0 = b1[lane], b1v1 = b1[lane + 32];
    float w2v0 = W2[lane], w2v1 = W2[lane + 32];
    float b2s = b2[0];

    __shared__ __align__(16) float sa[T1][128];
    __shared__ __align__(16) float sh[T1][128];
    __shared__ __align__(16) float part[T1][512];
    __shared__ __align__(16) float sOut[T1][128];

    for (int i = t; i < T1 * 128; i += 512) {
        int n = i >> 7, k = i & 127;
        sa[n][k] = g_agg1f[(base + n) * 128 + k];
        sh[n][k] = g_h0[(base + n) * 128 + k];
    }
    __syncthreads();

    // Phase A: quarter-row dots for all nodes
    for (int n = 0; n < T1; n++) {
        const ulonglong2* a2 = (const ulonglong2*)(sa[n] + hq * 32);
        const ulonglong2* h4 = (const ulonglong2*)(sh[n] + hq * 32);
        ull c0 = 0, c1 = 0, c2 = 0, c3 = 0;
        #pragma unroll
        for (int k = 0; k < 8; k++) {
            ulonglong2 pa = a2[k];
            ulonglong2 ph = h4[k];
            c0 = fma2(wl2[2*k],   pa.x, c0);
            c1 = fma2(wl2[2*k+1], pa.y, c1);
            c2 = fma2(wr2[2*k],   ph.x, c2);
            c3 = fma2(wr2[2*k+1], ph.y, c3);
        }
        part[n][t] = blj + ((red2(c0) + red2(c1)) + (red2(c2) + red2(c3)));
    }
    __syncthreads();

    // Phase B: warp w -> node w
    {
        int n = w;
        float v0 = part[n][lane]      + part[n][lane + 128] + part[n][lane + 256] + part[n][lane + 384];
        float v1 = part[n][lane + 32] + part[n][lane + 160] + part[n][lane + 288] + part[n][lane + 416];
        float v2 = part[n][lane + 64] + part[n][lane + 192] + part[n][lane + 320] + part[n][lane + 448];
        float v3 = part[n][lane + 96] + part[n][lane + 224] + part[n][lane + 352] + part[n][lane + 480];
        float s1 = (v0 + v1) + (v2 + v3);
        float s2 = (v0*v0 + v1*v1) + (v2*v2 + v3*v3);
        #pragma unroll
        for (int o = 16; o > 0; o >>= 1) {
            s1 += __shfl_xor_sync(0xFFFFFFFFu, s1, o);
            s2 += __shfl_xor_sync(0xFFFFFFFFu, s2, o);
        }
        float mu = s1 * (1.f / 128.f);
        float var = s2 * (1.f / 128.f) - mu * mu;
        float rstd = rsqrtf(var + LN_EPS);
        sOut[n][lane]      = fmaxf((v0 - mu) * rstd * gv[0] + bv[0], 0.f);
        sOut[n][lane + 32] = fmaxf((v1 - mu) * rstd * gv[1] + bv[1], 0.f);
        sOut[n][lane + 64] = fmaxf((v2 - mu) * rstd * gv[2] + bv[2], 0.f);
        sOut[n][lane + 96] = fmaxf((v3 - mu) * rstd * gv[3] + bv[3], 0.f);
    }
    __syncthreads();

    // Phase C1: head segment dots (part[n][t] == seg q of out-feat m)
    // Segment is 16 floats = 4 ulonglong2 -> k < 4 (this was the R12 bug: k < 2).
    for (int n = 0; n < T1; n++) {
        const ulonglong2* s2p = (const ulonglong2*)(sOut[n] + q * 16);
        ull c0 = 0, c1 = 0;
        #pragma unroll
        for (int k = 0; k < 4; k++) {
            ulonglong2 pv = s2p[k];
            c0 = fma2(w1p[2*k],   pv.x, c0);
            c1 = fma2(w1p[2*k+1], pv.y, c1);
        }
        part[n][t] = red2(c0) + red2(c1);
    }
    __syncthreads();

    // Phase C2: warp w -> node w
    {
        int n = w;
        float h0 = b1v0, h1 = b1v1;
        #pragma unroll
        for (int qq = 0; qq < 8; qq++) {
            h0 += part[n][qq * 64 + lane];
            h1 += part[n][qq * 64 + 32 + lane];
        }
        float z = fmaxf(h0, 0.f) * w2v0 + fmaxf(h1, 0.f) * w2v1;
        #pragma unroll
        for (int o = 16; o > 0; o >>= 1)
            z += __shfl_xor_sync(0xFFFFFFFFu, z, o);
        if (lane == 0)
            out[base + n] = 1.f / (1.f + expf(-(z + b2s)));
    }
}

// ---------------- launch ----------------
extern "C" void kernel_launch(void* const* d_in, const int* in_sizes, int n_in,
                              void* d_out, int out_size) {
    const float* x   = (const float*)d_in[0];
    const void*  ei  = d_in[1];
    const float* Wl0 = (const float*)d_in[2];
    const float* bl0 = (const float*)d_in[3];
    const float* Wr0 = (const float*)d_in[4];
    const float* g0  = (const float*)d_in[5];
    const float* be0 = (const float*)d_in[6];
    const float* Wl1 = (const float*)d_in[7];
    const float* bl1 = (const float*)d_in[8];
    const float* Wr1 = (const float*)d_in[9];
    const float* g1  = (const float*)d_in[10];
    const float* be1 = (const float*)d_in[11];
    const float* W1  = (const float*)d_in[12];
    const float* b1  = (const float*)d_in[13];
    const float* W2  = (const float*)d_in[14];
    const float* b2  = (const float*)d_in[15];
    float* out = (float*)d_out;

    k_init2<<<(NN + 1023) / 1024, 1024>>>((const int*)ei);   // 1
    k_count<<<(EE + 255) / 256, 256>>>(ei);                  // 2
    k_scan1<<<NB0, SB>>>();                                  // 3
    k_scan23<<<NB0, SB>>>();                                 // 4
    k_fill<<<(EE + 255) / 256, 256>>>(ei);                   // 5
    k_agg0<<<(NN * 32 + 255) / 256, 256>>>(x);               // 6
    k_sage0<<<NN / T0, 256>>>(x, Wl0, bl0, Wr0, g0, be0);    // 7
    k_agg1<<<(NN * 32 + 255) / 256, 256>>>();                // 8
    k_sage1<<<NN / T1, 512>>>(Wl1, bl1, Wr1, g1, be1, W1, b1, W2, b2, out);  // 9
}